// round 8
// baseline (speedup 1.0000x reference)
#include <cuda_runtime.h>
#include <cuda_bf16.h>
#include <cstdint>

// ---------------------------------------------------------------------------
// NRI decoder step. Edge MLPs on HMMA (mma.sync bf16, 2-way split for accuracy)
// Shapes: B=128, N=64, K=2, VDIM=EDIM=32, HID=64, E=4032, BE=516096
// Output: [dv (262144) | de (16515072) | zeros (1032192)] floats
// ---------------------------------------------------------------------------

#define BN_  128
#define NN_  64
#define EE_  4032
#define BE_  516096
#define DV_ELEMS   262144
#define ZERO_ELEMS 1032192
#define DE_OFF     262144
#define ZERO_OFF   16777216

using ull = unsigned long long;

// scratch (device globals; no runtime allocation)
__device__ float g_O[(size_t)BE_ * 64];      // edge MLP outputs, EDGE-major [ge][k*32+ch]
__device__ float g_agg[BN_ * NN_ * 32];
__device__ float g_ov[BN_ * NN_ * 32];
__device__ float g_esum[64], g_esq[64];
__device__ float g_nsum[32], g_nsq[32];
__device__ float g_ea[64], g_ec[64];
__device__ float g_na[32], g_nc[32];
// pre-split, pre-transposed weights (B-operand layout [k][n][f], k contiguous)
__device__ __nv_bfloat16 g_w1h[8192], g_w1l[8192];   // [2][64 n][64 f]
__device__ __nv_bfloat16 g_w2h[4096], g_w2l[4096];   // [2][32 n][64 h]

__device__ __forceinline__ float elu_f(float x) {
    return x > 0.f ? x : (__expf(x) - 1.f);
}
__device__ __forceinline__ ull pk(float a, float b) {
    ull r; asm("mov.b64 %0,{%1,%2};" : "=l"(r) : "f"(a), "f"(b)); return r;
}
__device__ __forceinline__ void upk(float& a, float& b, ull v) {
    asm("mov.b64 {%0,%1},%2;" : "=f"(a), "=f"(b) : "l"(v));
}
__device__ __forceinline__ ull fma2(ull a, ull b, ull c) {
    ull d; asm("fma.rn.f32x2 %0,%1,%2,%3;" : "=l"(d) : "l"(a), "l"(b), "l"(c)); return d;
}
__device__ __forceinline__ uint32_t smem_u32(const void* p) {
    uint32_t a;
    asm("{ .reg .u64 t; cvta.to.shared.u64 t, %1; cvt.u32.u64 %0, t; }" : "=r"(a) : "l"(p));
    return a;
}
__device__ __forceinline__ void split2(float a, float b, uint32_t& h, uint32_t& l) {
    __nv_bfloat16 ah = __float2bfloat16(a), bh = __float2bfloat16(b);
    float ar = a - __bfloat162float(ah), br = b - __bfloat162float(bh);
    __nv_bfloat16 al = __float2bfloat16(ar), bl = __float2bfloat16(br);
    h = (uint32_t)__bfloat16_as_ushort(ah) | ((uint32_t)__bfloat16_as_ushort(bh) << 16);
    l = (uint32_t)__bfloat16_as_ushort(al) | ((uint32_t)__bfloat16_as_ushort(bl) << 16);
}

// ---- warp MMA helpers ------------------------------------------------------
__device__ __forceinline__ void ldsm_x2(uint32_t addr, uint32_t r[2]) {
    asm volatile("ldmatrix.sync.aligned.m8n8.x2.shared.b16 {%0,%1}, [%2];"
        : "=r"(r[0]), "=r"(r[1]) : "r"(addr));
}
__device__ __forceinline__ void mma16816(float c[4], const uint32_t a[4], const uint32_t b[2]) {
    asm volatile("mma.sync.aligned.m16n8k16.row.col.f32.bf16.bf16.f32 "
        "{%0,%1,%2,%3}, {%4,%5,%6,%7}, {%8,%9}, {%0,%1,%2,%3};"
        : "+f"(c[0]), "+f"(c[1]), "+f"(c[2]), "+f"(c[3])
        : "r"(a[0]), "r"(a[1]), "r"(a[2]), "r"(a[3]), "r"(b[0]), "r"(b[1]));
}

// ---------------------------------------------------------------------------
// 0) zero stats + zeros output
// ---------------------------------------------------------------------------
__global__ void zero_kernel(float* __restrict__ zout) {
    int idx = blockIdx.x * 256 + threadIdx.x;
    if (idx < ZERO_ELEMS) zout[idx] = 0.f;
    if (idx < 64) { g_esum[idx] = 0.f; g_esq[idx] = 0.f; }
    if (idx < 32) { g_nsum[idx] = 0.f; g_nsq[idx] = 0.f; }
}

// ---------------------------------------------------------------------------
// 0b) weight prep: transpose to [k][n][f] + bf16 hi/lo split
// ---------------------------------------------------------------------------
__global__ void prep_w(const float* __restrict__ w1, const float* __restrict__ w2) {
    int t = blockIdx.x * 256 + threadIdx.x;
    if (t < 8192) {          // g_w1*[t], t = (k*64+n)*64+f  <-  w1[(k*64+f)*64+n]
        int f = t & 63, n = (t >> 6) & 63, k = t >> 12;
        float v = w1[(k * 64 + f) * 64 + n];
        __nv_bfloat16 h = __float2bfloat16(v);
        g_w1h[t] = h;
        g_w1l[t] = __float2bfloat16(v - __bfloat162float(h));
    }
    if (t < 4096) {          // g_w2*[t], t = (k*32+n)*64+h  <-  w2[(k*64+h)*32+n]
        int hh = t & 63, n = (t >> 6) & 31, k = t >> 11;
        float v = w2[(k * 64 + hh) * 32 + n];
        __nv_bfloat16 h = __float2bfloat16(v);
        g_w2h[t] = h;
        g_w2l[t] = __float2bfloat16(v - __bfloat162float(h));
    }
}

// ---------------------------------------------------------------------------
// 1) edge2node aggregation
// ---------------------------------------------------------------------------
__global__ __launch_bounds__(256) void agg_kernel(const float* __restrict__ e0) {
    int gw = (blockIdx.x * 256 + threadIdx.x) >> 5;
    int lane = threadIdx.x & 31;
    int b = gw >> 6, j = gw & 63;
    const float* base = e0 + (size_t)b * (NN_ * 63 * 32) + lane;
    float acc = 0.f;
    #pragma unroll 4
    for (int i = 0; i < 64; ++i) {
        if (i == j) continue;
        int jj = (j < i) ? j : j - 1;
        acc += base[(i * 63 + jj) * 32];
    }
    g_agg[gw * 32 + lane] = acc * (1.f / 64.f);
}

// ---------------------------------------------------------------------------
// 2) node MLP: 64 nodes/block, 2 threads per node (output-channel halves)
// ---------------------------------------------------------------------------
__global__ __launch_bounds__(128) void node_mlp1(
    const float* __restrict__ w1, const float* __restrict__ b1,
    const float* __restrict__ w2, const float* __restrict__ b2)
{
    __shared__ float W1s[2048];          // [32 f][64 h]
    __shared__ float W2s[2048];          // [64 h][32 o]
    __shared__ float B1s[64], B2s[32];
    __shared__ float Xs[64 * 33];
    __shared__ float Hs[64 * 65];
    __shared__ float SSUM[32], SSQ[32];

    const int tid = threadIdx.x;
    const int p   = tid >> 6;            // half index (0/1)
    const int nl  = tid & 63;            // node within block
    for (int idx = tid; idx < 2048; idx += 128) { W1s[idx] = w1[idx]; W2s[idx] = w2[idx]; }
    if (tid < 64) B1s[tid] = b1[tid];
    if (tid < 32) { B2s[tid] = b2[tid]; SSUM[tid] = 0.f; SSQ[tid] = 0.f; }
    for (int idx = tid; idx < 2048; idx += 128)
        Xs[(idx >> 5) * 33 + (idx & 31)] = g_agg[blockIdx.x * 2048 + idx];
    __syncthreads();

    const int node = blockIdx.x * 64 + nl;
    const unsigned lane = tid & 31;

    // layer 1: this thread computes h[32p .. 32p+31]
    ull h2[16];
    #pragma unroll
    for (int j = 0; j < 16; ++j) h2[j] = pk(B1s[32 * p + 2 * j], B1s[32 * p + 2 * j + 1]);
    #pragma unroll 4
    for (int f = 0; f < 32; ++f) {
        float xf = Xs[nl * 33 + f];
        ull x2 = pk(xf, xf);
        const ulonglong2* wq = reinterpret_cast<const ulonglong2*>(W1s + f * 64 + 32 * p);
        #pragma unroll
        for (int j = 0; j < 8; ++j) {
            ulonglong2 q = wq[j];
            h2[2 * j]     = fma2(x2, q.x, h2[2 * j]);
            h2[2 * j + 1] = fma2(x2, q.y, h2[2 * j + 1]);
        }
    }
    #pragma unroll
    for (int j = 0; j < 16; ++j) {
        float a, c; upk(a, c, h2[j]);
        Hs[nl * 65 + 32 * p + 2 * j]     = elu_f(a);
        Hs[nl * 65 + 32 * p + 2 * j + 1] = elu_f(c);
    }
    __syncthreads();

    // layer 2: this thread computes o[16p .. 16p+15]
    ull o2[8];
    #pragma unroll
    for (int j = 0; j < 8; ++j) o2[j] = pk(B2s[16 * p + 2 * j], B2s[16 * p + 2 * j + 1]);
    #pragma unroll 4
    for (int hh = 0; hh < 64; ++hh) {
        float hv = Hs[nl * 65 + hh];
        ull hb = pk(hv, hv);
        const ulonglong2* wq = reinterpret_cast<const ulonglong2*>(W2s + hh * 32 + 16 * p);
        #pragma unroll
        for (int j = 0; j < 4; ++j) {
            ulonglong2 q = wq[j];
            o2[2 * j]     = fma2(hb, q.x, o2[2 * j]);
            o2[2 * j + 1] = fma2(hb, q.y, o2[2 * j + 1]);
        }
    }
    #pragma unroll
    for (int j = 0; j < 8; ++j) {
        float a, c; upk(a, c, o2[j]);
        a = elu_f(a); c = elu_f(c);
        const int ch = 16 * p + 2 * j;
        g_ov[node * 32 + ch]     = a;
        g_ov[node * 32 + ch + 1] = c;
        float s0 = a, q0 = a * a, s1 = c, q1 = c * c;
        #pragma unroll
        for (int off = 16; off; off >>= 1) {
            s0 += __shfl_xor_sync(0xffffffffu, s0, off);
            q0 += __shfl_xor_sync(0xffffffffu, q0, off);
            s1 += __shfl_xor_sync(0xffffffffu, s1, off);
            q1 += __shfl_xor_sync(0xffffffffu, q1, off);
        }
        if (lane == 0) {
            atomicAdd(&SSUM[ch], s0);     atomicAdd(&SSQ[ch], q0);
            atomicAdd(&SSUM[ch + 1], s1); atomicAdd(&SSQ[ch + 1], q1);
        }
    }
    __syncthreads();
    if (tid < 32) { atomicAdd(&g_nsum[tid], SSUM[tid]); atomicAdd(&g_nsq[tid], SSQ[tid]); }
}

// ---------------------------------------------------------------------------
// 3) edge MLPs on HMMA. A-operand fragments gathered DIRECTLY from v0 via
//    float2 LDG + in-register bf16 split (no X smem, no A-side ldmatrix).
//    Only weights live in smem. One barrier total.
// smem (bytes):
//   0      W1h [2k][64 n][72 b16]   18432
//   18432  W1l                       18432
//   36864  W2h [2k][32 n][72]        9216
//   46080  W2l                       9216
//   55296  CTRL: SB1[128] SB2[64] SSUM[64] SSQ[64]   1280
// ---------------------------------------------------------------------------
#define W1H_B  0
#define W1L_B  18432
#define W2H_B  36864
#define W2L_B  46080
#define CTRL_B 55296
#define EH_SMEM 56576

__global__ __launch_bounds__(128, 3) void edge_hmma(
    const float* __restrict__ v0,
    const float* __restrict__ b1, const float* __restrict__ b2)
{
    extern __shared__ char sm[];
    const uint32_t smb = smem_u32(sm);
    const int tid = threadIdx.x, wid = tid >> 5, lid = tid & 31;
    const int R0 = wid * 32;

    float* SB1  = (float*)(sm + CTRL_B);           // [2][64]
    float* SB2  = (float*)(sm + CTRL_B + 512);     // [2][32]
    float* SSUM = (float*)(sm + CTRL_B + 768);
    float* SSQ  = (float*)(sm + CTRL_B + 1024);

    // ---- weight + bias loads ---------------------------------------------
    {
        uint32_t* W1hw = (uint32_t*)(sm + W1H_B);
        uint32_t* W1lw = (uint32_t*)(sm + W1L_B);
        uint32_t* W2hw = (uint32_t*)(sm + W2H_B);
        uint32_t* W2lw = (uint32_t*)(sm + W2L_B);
        const uint32_t* gw1h = (const uint32_t*)g_w1h;
        const uint32_t* gw1l = (const uint32_t*)g_w1l;
        const uint32_t* gw2h = (const uint32_t*)g_w2h;
        const uint32_t* gw2l = (const uint32_t*)g_w2l;
        for (int idx = tid; idx < 4096; idx += 128) {       // W1: [k][64n][32w]
            int w = idx & 31, n = (idx >> 5) & 63, kz = idx >> 11;
            W1hw[kz * 2304 + n * 36 + w] = gw1h[idx];
            W1lw[kz * 2304 + n * 36 + w] = gw1l[idx];
        }
        for (int idx = tid; idx < 2048; idx += 128) {       // W2: [k][32n][32w]
            int w = idx & 31, n = (idx >> 5) & 31, kz = idx >> 10;
            W2hw[kz * 1152 + n * 36 + w] = gw2h[idx];
            W2lw[kz * 1152 + n * 36 + w] = gw2l[idx];
        }
        if (tid < 128) SB1[tid] = b1[tid];
        if (tid < 64)  { SB2[tid] = b2[tid]; SSUM[tid] = 0.f; SSQ[tid] = 0.f; }
    }
    __syncthreads();

    const int g  = lid >> 2;       // fragment row within 8
    const int cq = lid & 3;        // fragment col pair

    // ---- decode this lane's 4 edge rows (mt in {0,1} x {g, g+8}) ---------
    const int geT = blockIdx.x * 128 + R0;
    int offR[4], offS[4];          // float offsets into v0
    #pragma unroll
    for (int m2 = 0; m2 < 4; ++m2) {
        int mt = m2 >> 1, rs = (m2 & 1) * 8;
        int gid = geT + mt * 16 + g + rs;
        int b = gid / EE_;
        int e = gid - b * EE_;
        int i0 = e / 63, jj = e - i0 * 63;
        int rc = (jj < i0) ? jj : jj + 1;
        offR[m2] = (b * 64 + rc) * 32;
        offS[m2] = (b * 64 + i0) * 32;
    }

    // B-operand ldmatrix lane bases
    const int brow = lid & 7;
    const int bcol = ((lid >> 3) & 1) * 16;
    const uint32_t bW1h = smb + W1H_B + brow * 144 + bcol;
    const uint32_t bW1l = smb + W1L_B + brow * 144 + bcol;
    const uint32_t bW2h = smb + W2H_B + brow * 144 + bcol;
    const uint32_t bW2l = smb + W2L_B + brow * 144 + bcol;

    // ---- main loop: no barriers inside -----------------------------------
    #pragma unroll 1
    for (int k = 0; k < 2; ++k) {
        const float* SB1k = SB1 + k * 64;
        const float* SB2k = SB2 + k * 32;
        const uint32_t w1hk = bW1h + k * 9216;
        const uint32_t w1lk = bW1l + k * 9216;
        const uint32_t w2hk = bW2h + k * 4608;
        const uint32_t w2lk = bW2l + k * 4608;

        // layer 1: H[32,64] = X @ W1^T  (Xh@Wh + Xh@Wl + Xl@Wh)
        float acc[2][8][4];
        #pragma unroll
        for (int mt = 0; mt < 2; ++mt)
            #pragma unroll
            for (int nt = 0; nt < 8; ++nt)
                #pragma unroll
                for (int q = 0; q < 4; ++q) acc[mt][nt][q] = 0.f;

        #pragma unroll
        for (int kk = 0; kk < 4; ++kk) {
            // gather A fragments straight from v0
            const int ncol = (kk & 1) * 16 + 2 * cq;
            uint32_t Ah[2][4], Al[2][4];
            #pragma unroll
            for (int mt = 0; mt < 2; ++mt) {
                const int o0 = (kk < 2) ? offR[mt * 2]     : offS[mt * 2];
                const int o1 = (kk < 2) ? offR[mt * 2 + 1] : offS[mt * 2 + 1];
                float2 f0 = *(const float2*)(v0 + o0 + ncol);
                float2 f1 = *(const float2*)(v0 + o1 + ncol);
                float2 f2 = *(const float2*)(v0 + o0 + ncol + 8);
                float2 f3 = *(const float2*)(v0 + o1 + ncol + 8);
                split2(f0.x, f0.y, Ah[mt][0], Al[mt][0]);
                split2(f1.x, f1.y, Ah[mt][1], Al[mt][1]);
                split2(f2.x, f2.y, Ah[mt][2], Al[mt][2]);
                split2(f3.x, f3.y, Ah[mt][3], Al[mt][3]);
            }
            #pragma unroll
            for (int nt = 0; nt < 8; ++nt) {
                uint32_t bh[2], bl[2];
                ldsm_x2(w1hk + nt * 1152 + kk * 32, bh);
                ldsm_x2(w1lk + nt * 1152 + kk * 32, bl);
                mma16816(acc[0][nt], Ah[0], bh);
                mma16816(acc[1][nt], Ah[1], bh);
                mma16816(acc[0][nt], Ah[0], bl);
                mma16816(acc[1][nt], Ah[1], bl);
                mma16816(acc[0][nt], Al[0], bh);
                mma16816(acc[1][nt], Al[1], bh);
            }
        }

        // epilogue 1: bias+ELU, repack C fragments -> layer-2 A operands
        uint32_t A2h[2][4][4], A2l[2][4][4];
        #pragma unroll
        for (int mt = 0; mt < 2; ++mt) {
            #pragma unroll
            for (int kk = 0; kk < 4; ++kk) {
                const int c0 = 16 * kk + 2 * cq;
                float v00 = elu_f(acc[mt][2 * kk][0] + SB1k[c0]);
                float v01 = elu_f(acc[mt][2 * kk][1] + SB1k[c0 + 1]);
                float v10 = elu_f(acc[mt][2 * kk][2] + SB1k[c0]);
                float v11 = elu_f(acc[mt][2 * kk][3] + SB1k[c0 + 1]);
                float w00 = elu_f(acc[mt][2 * kk + 1][0] + SB1k[c0 + 8]);
                float w01 = elu_f(acc[mt][2 * kk + 1][1] + SB1k[c0 + 9]);
                float w10 = elu_f(acc[mt][2 * kk + 1][2] + SB1k[c0 + 8]);
                float w11 = elu_f(acc[mt][2 * kk + 1][3] + SB1k[c0 + 9]);
                split2(v00, v01, A2h[mt][kk][0], A2l[mt][kk][0]);
                split2(v10, v11, A2h[mt][kk][1], A2l[mt][kk][1]);
                split2(w00, w01, A2h[mt][kk][2], A2l[mt][kk][2]);
                split2(w10, w11, A2h[mt][kk][3], A2l[mt][kk][3]);
            }
        }

        // layer 2: O[32,32] = H @ W2^T  (Hh@Wh + Hh@Wl + Hl@Wh)
        float ac2[2][4][4];
        #pragma unroll
        for (int mt = 0; mt < 2; ++mt)
            #pragma unroll
            for (int nt = 0; nt < 4; ++nt)
                #pragma unroll
                for (int q = 0; q < 4; ++q) ac2[mt][nt][q] = 0.f;

        #pragma unroll
        for (int kk = 0; kk < 4; ++kk) {
            #pragma unroll
            for (int nt = 0; nt < 4; ++nt) {
                uint32_t bh[2], bl[2];
                ldsm_x2(w2hk + nt * 1152 + kk * 32, bh);
                ldsm_x2(w2lk + nt * 1152 + kk * 32, bl);
                mma16816(ac2[0][nt], A2h[0][kk], bh);
                mma16816(ac2[1][nt], A2h[1][kk], bh);
                mma16816(ac2[0][nt], A2h[0][kk], bl);
                mma16816(ac2[1][nt], A2h[1][kk], bl);
                mma16816(ac2[0][nt], A2l[0][kk], bh);
                mma16816(ac2[1][nt], A2l[1][kk], bh);
            }
        }

        // epilogue 2: bias+ELU, edge-major float2 stores + register BN stats
        float sl[8], ql[8];
        #pragma unroll
        for (int j = 0; j < 8; ++j) { sl[j] = 0.f; ql[j] = 0.f; }
        #pragma unroll
        for (int mt = 0; mt < 2; ++mt) {
            const int ge0 = geT + mt * 16 + g;
            #pragma unroll
            for (int nt = 0; nt < 4; ++nt) {
                const int col = nt * 8 + 2 * cq;
                float v00 = elu_f(ac2[mt][nt][0] + SB2k[col]);
                float v01 = elu_f(ac2[mt][nt][1] + SB2k[col + 1]);
                float v10 = elu_f(ac2[mt][nt][2] + SB2k[col]);
                float v11 = elu_f(ac2[mt][nt][3] + SB2k[col + 1]);
                *(float2*)(g_O + (size_t)ge0 * 64 + k * 32 + col)       = make_float2(v00, v01);
                *(float2*)(g_O + (size_t)(ge0 + 8) * 64 + k * 32 + col) = make_float2(v10, v11);
                sl[nt * 2]     += v00 + v10;
                ql[nt * 2]     += v00 * v00 + v10 * v10;
                sl[nt * 2 + 1] += v01 + v11;
                ql[nt * 2 + 1] += v01 * v01 + v11 * v11;
            }
        }
        #pragma unroll
        for (int j = 0; j < 8; ++j) {
            #pragma unroll
            for (int off = 4; off < 32; off <<= 1) {
                sl[j] += __shfl_xor_sync(0xffffffffu, sl[j], off);
                ql[j] += __shfl_xor_sync(0xffffffffu, ql[j], off);
            }
        }
        if (lid < 4) {
            #pragma unroll
            for (int nt = 0; nt < 4; ++nt) {
                atomicAdd(&SSUM[k * 32 + nt * 8 + 2 * lid],     sl[nt * 2]);
                atomicAdd(&SSQ [k * 32 + nt * 8 + 2 * lid],     ql[nt * 2]);
                atomicAdd(&SSUM[k * 32 + nt * 8 + 2 * lid + 1], sl[nt * 2 + 1]);
                atomicAdd(&SSQ [k * 32 + nt * 8 + 2 * lid + 1], ql[nt * 2 + 1]);
            }
        }
    }

    __syncthreads();
    if (tid < 64) { atomicAdd(&g_esum[tid], SSUM[tid]); atomicAdd(&g_esq[tid], SSQ[tid]); }
}

// ---------------------------------------------------------------------------
// 4) finalize BN stats -> affine
// ---------------------------------------------------------------------------
__global__ void finalize_kernel(const float* __restrict__ eg, const float* __restrict__ eb,
                                const float* __restrict__ vg, const float* __restrict__ vb)
{
    int t = threadIdx.x;
    if (t < 64) {
        const float inv_cnt = 1.f / (float)BE_;
        float mu = g_esum[t] * inv_cnt;
        float var = g_esq[t] * inv_cnt - mu * mu;
        float a = eg[t] * rsqrtf(var + 1e-5f);
        g_ea[t] = a; g_ec[t] = eb[t] - mu * a;
    }
    if (t < 32) {
        const float inv_cnt = 1.f / 8192.f;
        float mu = g_nsum[t] * inv_cnt;
        float var = g_nsq[t] * inv_cnt - mu * mu;
        float a = vg[t] * rsqrtf(var + 1e-5f);
        g_na[t] = a; g_nc[t] = vb[t] - mu * a;
    }
}

// ---------------------------------------------------------------------------
// 5) normalize node output -> dv
// ---------------------------------------------------------------------------
__global__ void node_norm(float* __restrict__ dv) {
    int idx = blockIdx.x * 256 + threadIdx.x;
    if (idx < DV_ELEMS) {
        int c = idx & 31;
        dv[idx] = g_ov[idx] * g_na[c] + g_nc[c];
    }
}

// ---------------------------------------------------------------------------
// 6) normalize + mask + sum over k -> de.  Pure streaming (edge-major g_O):
//    thread = one edge; reads 256B contiguous, writes 128B contiguous.
// ---------------------------------------------------------------------------
__global__ __launch_bounds__(256) void edge_out(const float* __restrict__ et,
                                                float* __restrict__ de)
{
    __shared__ float A[64], C[64];
    const int tid = threadIdx.x;
    if (tid < 64) { A[tid] = g_ea[tid]; C[tid] = g_ec[tid]; }
    __syncthreads();

    const int ge = blockIdx.x * 256 + tid;
    const float2 w = reinterpret_cast<const float2*>(et)[ge];
    const float4* src = (const float4*)(g_O + (size_t)ge * 64);
    float4* dst = (float4*)(de + (size_t)ge * 32);
    #pragma unroll
    for (int i = 0; i < 8; ++i) {
        float4 x0 = src[i];          // k=0, channels 4i..4i+3
        float4 x1 = src[8 + i];      // k=1
        float4 o;
        o.x = (A[4*i]   * x0.x + C[4*i])   * w.x + (A[32+4*i]   * x1.x + C[32+4*i])   * w.y;
        o.y = (A[4*i+1] * x0.y + C[4*i+1]) * w.x + (A[32+4*i+1] * x1.y + C[32+4*i+1]) * w.y;
        o.z = (A[4*i+2] * x0.z + C[4*i+2]) * w.x + (A[32+4*i+2] * x1.z + C[32+4*i+2]) * w.y;
        o.w = (A[4*i+3] * x0.w + C[4*i+3]) * w.x + (A[32+4*i+3] * x1.w + C[32+4*i+3]) * w.y;
        dst[i] = o;
    }
}

// ---------------------------------------------------------------------------
extern "C" void kernel_launch(void* const* d_in, const int* in_sizes, int n_in,
                              void* d_out, int out_size)
{
    const float* v0   = (const float*)d_in[0];
    const float* e0   = (const float*)d_in[1];
    const float* et   = (const float*)d_in[2];
    const float* vW1  = (const float*)d_in[3];
    const float* vb1  = (const float*)d_in[4];
    const float* vW2  = (const float*)d_in[5];
    const float* vb2  = (const float*)d_in[6];
    const float* vg   = (const float*)d_in[7];
    const float* vbet = (const float*)d_in[8];
    const float* eW1  = (const float*)d_in[9];
    const float* eb1  = (const float*)d_in[10];
    const float* eW2  = (const float*)d_in[11];
    const float* eb2  = (const float*)d_in[12];
    const float* eg   = (const float*)d_in[13];
    const float* ebet = (const float*)d_in[14];
    float* out = (float*)d_out;

    cudaFuncSetAttribute(edge_hmma, cudaFuncAttributeMaxDynamicSharedMemorySize, EH_SMEM);
    cudaFuncSetAttribute(edge_hmma, cudaFuncAttributePreferredSharedMemoryCarveout, 100);

    zero_kernel<<<4032, 256>>>(out + ZERO_OFF);
    prep_w<<<32, 256>>>(eW1, eW2);
    agg_kernel<<<1024, 256>>>(e0);
    node_mlp1<<<128, 128>>>(vW1, vb1, vW2, vb2);
    edge_hmma<<<4032, 128, EH_SMEM>>>(v0, eb1, eb2);
    finalize_kernel<<<1, 64>>>(eg, ebet, vg, vbet);
    node_norm<<<1024, 256>>>(out);
    edge_out<<<2016, 256>>>(et, out + DE_OFF);

    (void)in_sizes; (void)n_in; (void)out_size;
}

// round 9
// speedup vs baseline: 1.1651x; 1.1651x over previous
#include <cuda_runtime.h>
#include <cuda_bf16.h>
#include <cstdint>

// ---------------------------------------------------------------------------
// NRI decoder step. Edge MLPs on HMMA (mma.sync bf16, 2-way split for accuracy)
// Shapes: B=128, N=64, K=2, VDIM=EDIM=32, HID=64, E=4032, BE=516096
// Output: [dv (262144) | de (16515072) | zeros (1032192)] floats
// ---------------------------------------------------------------------------

#define BN_  128
#define NN_  64
#define EE_  4032
#define BE_  516096
#define DV_ELEMS   262144
#define ZERO_ELEMS 1032192
#define DE_OFF     262144
#define ZERO_OFF   16777216

using ull = unsigned long long;

// scratch (device globals; no runtime allocation)
__device__ float g_O[2 * 32 * BE_];          // edge MLP outputs [k*32+ch][ge]
__device__ float g_agg[BN_ * NN_ * 32];
__device__ float g_ov[BN_ * NN_ * 32];
__device__ float g_esum[64], g_esq[64];
__device__ float g_nsum[32], g_nsq[32];
// pre-split, pre-transposed weights (B-operand layout [k][n][f], k contiguous)
__device__ __nv_bfloat16 g_w1h[8192], g_w1l[8192];   // [2][64 n][64 f]
__device__ __nv_bfloat16 g_w2h[4096], g_w2l[4096];   // [2][32 n][64 h]

__device__ __forceinline__ float elu_f(float x) {
    return x > 0.f ? x : (__expf(x) - 1.f);
}
__device__ __forceinline__ ull pk(float a, float b) {
    ull r; asm("mov.b64 %0,{%1,%2};" : "=l"(r) : "f"(a), "f"(b)); return r;
}
__device__ __forceinline__ void upk(float& a, float& b, ull v) {
    asm("mov.b64 {%0,%1},%2;" : "=f"(a), "=f"(b) : "l"(v));
}
__device__ __forceinline__ ull fma2(ull a, ull b, ull c) {
    ull d; asm("fma.rn.f32x2 %0,%1,%2,%3;" : "=l"(d) : "l"(a), "l"(b), "l"(c)); return d;
}
__device__ __forceinline__ uint32_t smem_u32(const void* p) {
    uint32_t a;
    asm("{ .reg .u64 t; cvta.to.shared.u64 t, %1; cvt.u32.u64 %0, t; }" : "=r"(a) : "l"(p));
    return a;
}
// fast 2-way bf16 split: h = bf16x2{lo=a,hi=b}; l = bf16x2 of residuals
__device__ __forceinline__ void split2(float a, float b, uint32_t& h, uint32_t& l) {
    uint32_t hh;
    asm("cvt.rn.bf16x2.f32 %0, %1, %2;" : "=r"(hh) : "f"(b), "f"(a));
    float fa = __uint_as_float(hh << 16);
    float fb = __uint_as_float(hh & 0xFFFF0000u);
    float ra = a - fa, rb = b - fb;
    uint32_t ll;
    asm("cvt.rn.bf16x2.f32 %0, %1, %2;" : "=r"(ll) : "f"(rb), "f"(ra));
    h = hh; l = ll;
}

// ---- warp MMA helpers ------------------------------------------------------
__device__ __forceinline__ void ldsm_x4(uint32_t addr, uint32_t r[4]) {
    asm volatile("ldmatrix.sync.aligned.m8n8.x4.shared.b16 {%0,%1,%2,%3}, [%4];"
        : "=r"(r[0]), "=r"(r[1]), "=r"(r[2]), "=r"(r[3]) : "r"(addr));
}
__device__ __forceinline__ void ldsm_x2(uint32_t addr, uint32_t r[2]) {
    asm volatile("ldmatrix.sync.aligned.m8n8.x2.shared.b16 {%0,%1}, [%2];"
        : "=r"(r[0]), "=r"(r[1]) : "r"(addr));
}
__device__ __forceinline__ void mma16816(float c[4], const uint32_t a[4], const uint32_t b[2]) {
    asm volatile("mma.sync.aligned.m16n8k16.row.col.f32.bf16.bf16.f32 "
        "{%0,%1,%2,%3}, {%4,%5,%6,%7}, {%8,%9}, {%0,%1,%2,%3};"
        : "+f"(c[0]), "+f"(c[1]), "+f"(c[2]), "+f"(c[3])
        : "r"(a[0]), "r"(a[1]), "r"(a[2]), "r"(a[3]), "r"(b[0]), "r"(b[1]));
}

// ---------------------------------------------------------------------------
// A) fused pre-pass: zeros + stats init | weight prep | edge2node aggregation
//    grid = 4032 (zero) + 32 (prep) + 1024 (agg) = 5088 blocks x 256
// ---------------------------------------------------------------------------
__global__ __launch_bounds__(256) void prepass(
    const float* __restrict__ e0,
    const float* __restrict__ w1, const float* __restrict__ w2,
    float* __restrict__ zout)
{
    const int bx = blockIdx.x, tid = threadIdx.x;
    if (bx < 4032) {
        int idx = bx * 256 + tid;
        zout[idx] = 0.f;                        // ZERO_ELEMS = 4032*256 exactly
        if (bx == 0) {
            if (tid < 64) { g_esum[tid] = 0.f; g_esq[tid] = 0.f; }
            else if (tid < 96) { g_nsum[tid - 64] = 0.f; g_nsq[tid - 64] = 0.f; }
        }
        return;
    }
    if (bx < 4064) {
        int t = (bx - 4032) * 256 + tid;        // 8192 threads
        {   // w1: t = (k*64+n)*64+f  <-  w1[(k*64+f)*64+n]
            int f = t & 63, n = (t >> 6) & 63, k = t >> 12;
            float v = w1[(k * 64 + f) * 64 + n];
            __nv_bfloat16 h = __float2bfloat16(v);
            g_w1h[t] = h;
            g_w1l[t] = __float2bfloat16(v - __bfloat162float(h));
        }
        if (t < 4096) {  // w2: t = (k*32+n)*64+h  <-  w2[(k*64+h)*32+n]
            int hh = t & 63, n = (t >> 6) & 31, k = t >> 11;
            float v = w2[(k * 64 + hh) * 32 + n];
            __nv_bfloat16 h = __float2bfloat16(v);
            g_w2h[t] = h;
            g_w2l[t] = __float2bfloat16(v - __bfloat162float(h));
        }
        return;
    }
    {   // aggregation
        int gw = ((bx - 4064) * 256 + tid) >> 5;
        int lane = tid & 31;
        int b = gw >> 6, j = gw & 63;
        const float* base = e0 + (size_t)b * (NN_ * 63 * 32) + lane;
        float acc = 0.f;
        #pragma unroll 4
        for (int i = 0; i < 64; ++i) {
            if (i == j) continue;
            int jj = (j < i) ? j : j - 1;
            acc += base[(i * 63 + jj) * 32];
        }
        g_agg[gw * 32 + lane] = acc * (1.f / 64.f);
    }
}

// ---------------------------------------------------------------------------
// B) node MLP (64 nodes/block, 128 blocks)
// ---------------------------------------------------------------------------
__global__ __launch_bounds__(64) void node_mlp1(
    const float* __restrict__ w1, const float* __restrict__ b1,
    const float* __restrict__ w2, const float* __restrict__ b2)
{
    __shared__ float W1s[2048];
    __shared__ float W2s[2048];
    __shared__ float B1s[64], B2s[32];
    __shared__ float Xs[64 * 33];
    __shared__ float SSUM[32], SSQ[32];

    const int tid = threadIdx.x;
    for (int idx = tid; idx < 2048; idx += 64) { W1s[idx] = w1[idx]; W2s[idx] = w2[idx]; }
    if (tid < 64) B1s[tid] = b1[tid];
    if (tid < 32) { B2s[tid] = b2[tid]; SSUM[tid] = 0.f; SSQ[tid] = 0.f; }
    for (int idx = tid; idx < 2048; idx += 64)
        Xs[(idx >> 5) * 33 + (idx & 31)] = g_agg[blockIdx.x * 2048 + idx];
    __syncthreads();

    const int node = blockIdx.x * 64 + tid;
    const unsigned lane = tid & 31;

    ull h2[32];
    #pragma unroll
    for (int j = 0; j < 32; ++j) h2[j] = pk(B1s[2 * j], B1s[2 * j + 1]);
    #pragma unroll 4
    for (int f = 0; f < 32; ++f) {
        float xf = Xs[tid * 33 + f];
        ull x2 = pk(xf, xf);
        const ulonglong2* wq = reinterpret_cast<const ulonglong2*>(W1s + f * 64);
        #pragma unroll
        for (int j = 0; j < 16; ++j) {
            ulonglong2 q = wq[j];
            h2[2 * j]     = fma2(x2, q.x, h2[2 * j]);
            h2[2 * j + 1] = fma2(x2, q.y, h2[2 * j + 1]);
        }
    }
    float h[64];
    #pragma unroll
    for (int j = 0; j < 32; ++j) {
        float a, c; upk(a, c, h2[j]);
        h[2 * j] = elu_f(a); h[2 * j + 1] = elu_f(c);
    }
    ull o2[16];
    #pragma unroll
    for (int j = 0; j < 16; ++j) o2[j] = pk(B2s[2 * j], B2s[2 * j + 1]);
    #pragma unroll
    for (int hh = 0; hh < 64; ++hh) {
        ull hb = pk(h[hh], h[hh]);
        const ulonglong2* wq = reinterpret_cast<const ulonglong2*>(W2s + hh * 32);
        #pragma unroll
        for (int j = 0; j < 8; ++j) {
            ulonglong2 q = wq[j];
            o2[2 * j]     = fma2(hb, q.x, o2[2 * j]);
            o2[2 * j + 1] = fma2(hb, q.y, o2[2 * j + 1]);
        }
    }
    #pragma unroll
    for (int j = 0; j < 16; ++j) {
        float a, c; upk(a, c, o2[j]);
        a = elu_f(a); c = elu_f(c);
        g_ov[node * 32 + 2 * j]     = a;
        g_ov[node * 32 + 2 * j + 1] = c;
        float s0 = a, q0 = a * a, s1 = c, q1 = c * c;
        #pragma unroll
        for (int off = 16; off; off >>= 1) {
            s0 += __shfl_xor_sync(0xffffffffu, s0, off);
            q0 += __shfl_xor_sync(0xffffffffu, q0, off);
            s1 += __shfl_xor_sync(0xffffffffu, s1, off);
            q1 += __shfl_xor_sync(0xffffffffu, q1, off);
        }
        if (lane == 0) {
            atomicAdd(&SSUM[2 * j], s0);     atomicAdd(&SSQ[2 * j], q0);
            atomicAdd(&SSUM[2 * j + 1], s1); atomicAdd(&SSQ[2 * j + 1], q1);
        }
    }
    __syncthreads();
    if (tid < 32) { atomicAdd(&g_nsum[tid], SSUM[tid]); atomicAdd(&g_nsq[tid], SSQ[tid]); }
}

// ---------------------------------------------------------------------------
// C) edge MLPs on HMMA, barrier-free main loop (round-6 structure).
//    Bias pre-loaded into accumulators; fast bf16x2 splits.
// smem (bytes):
//   0      X_H [128][72 b16] (phase A) / W1h [2k][64 n][72] (phase B)  18432
//   18432  X_L [128][72]                                              18432
//   36864  W1l [2k][64][72]                                           18432
//   55296  W2h [2k][32][72]                                           9216
//   64512  W2l [2k][32][72]                                           9216
//   73728  CTRL: SB1[128] | SB2[64] | SSUM[64] | SSQ[64]              1280
// ---------------------------------------------------------------------------
#define XH_B   0
#define XL_B   18432
#define W1L_B  36864
#define W2H_B  55296
#define W2L_B  64512
#define CTRL_B 73728
#define EH_SMEM 75008

__global__ __launch_bounds__(128, 3) void edge_hmma(
    const float* __restrict__ v0,
    const float* __restrict__ b1, const float* __restrict__ b2)
{
    extern __shared__ char sm[];
    const uint32_t smb = smem_u32(sm);
    const int tid = threadIdx.x, wid = tid >> 5, lid = tid & 31;
    const int R0 = wid * 32;

    float* SB1  = (float*)(sm + CTRL_B);           // [2][64]
    float* SB2  = (float*)(sm + CTRL_B + 512);     // [2][32]
    float* SSUM = (float*)(sm + CTRL_B + 768);
    float* SSQ  = (float*)(sm + CTRL_B + 1024);

    // ---- phase A: build X tile (row = this thread's edge) ----------------
    const int ge = blockIdx.x * 128 + tid;
    const int b  = ge / EE_;
    const int e  = ge - b * EE_;
    const int i0 = e / 63, jj = e - i0 * 63;
    const int recv = (jj < i0) ? jj : jj + 1;
    const float4* vr = (const float4*)(v0 + (size_t)(b * 64 + recv) * 32);
    const float4* vs = (const float4*)(v0 + (size_t)(b * 64 + i0) * 32);
    {
        uint32_t* Xhw = (uint32_t*)(sm + XH_B);
        uint32_t* Xlw = (uint32_t*)(sm + XL_B);
        #pragma unroll
        for (int c = 0; c < 16; ++c) {
            float4 f = (c < 8) ? vr[c] : vs[c - 8];
            uint32_t h0, l0, h1, l1;
            split2(f.x, f.y, h0, l0);
            split2(f.z, f.w, h1, l1);
            Xhw[tid * 36 + 2 * c]     = h0;
            Xhw[tid * 36 + 2 * c + 1] = h1;
            Xlw[tid * 36 + 2 * c]     = l0;
            Xlw[tid * 36 + 2 * c + 1] = l1;
        }
    }
    // non-conflicting loads: W1l, W2h/l, biases, stat init
    {
        uint32_t* W1lw = (uint32_t*)(sm + W1L_B);
        uint32_t* W2hw = (uint32_t*)(sm + W2H_B);
        uint32_t* W2lw = (uint32_t*)(sm + W2L_B);
        const uint32_t* gw1l = (const uint32_t*)g_w1l;
        const uint32_t* gw2h = (const uint32_t*)g_w2h;
        const uint32_t* gw2l = (const uint32_t*)g_w2l;
        for (int idx = tid; idx < 4096; idx += 128) {       // W1l: [k][64n][32w]
            int w = idx & 31, n = (idx >> 5) & 63, kz = idx >> 11;
            W1lw[kz * 2304 + n * 36 + w] = gw1l[idx];
        }
        for (int idx = tid; idx < 2048; idx += 128) {       // W2: [k][32n][32w]
            int w = idx & 31, n = (idx >> 5) & 31, kz = idx >> 10;
            W2hw[kz * 1152 + n * 36 + w] = gw2h[idx];
            W2lw[kz * 1152 + n * 36 + w] = gw2l[idx];
        }
        if (tid < 128) SB1[tid] = b1[tid];
        if (tid < 64)  { SB2[tid] = b2[tid]; SSUM[tid] = 0.f; SSQ[tid] = 0.f; }
    }
    __syncthreads();

    // ---- lane-dependent ldmatrix address bases ---------------------------
    const int arow = (lid & 7) + ((lid >> 3) & 1) * 8;
    const int acol = (lid >> 4) * 16;
    const int brow = lid & 7;
    const int bcol = ((lid >> 3) & 1) * 16;
    const uint32_t aXh = smb + XH_B + (R0 + arow) * 144 + acol;
    const uint32_t aXl = smb + XL_B + (R0 + arow) * 144 + acol;
    const uint32_t bW1h = smb + XH_B + brow * 144 + bcol;   // after overlay
    const uint32_t bW1l = smb + W1L_B + brow * 144 + bcol;
    const uint32_t bW2h = smb + W2H_B + brow * 144 + bcol;
    const uint32_t bW2l = smb + W2L_B + brow * 144 + bcol;

    const int g  = lid >> 2;
    const int cq = lid & 3;

    // ---- cache X hi fragments (X_H dies after this) ----------------------
    uint32_t Ah[2][4][4];
    #pragma unroll
    for (int mt = 0; mt < 2; ++mt)
        #pragma unroll
        for (int kk = 0; kk < 4; ++kk)
            ldsm_x4(aXh + mt * 2304 + kk * 32, Ah[mt][kk]);
    __syncthreads();

    // ---- phase B: overlay W1h onto X_H region ----------------------------
    {
        uint32_t* W1hw = (uint32_t*)(sm + XH_B);
        const uint32_t* gw1h = (const uint32_t*)g_w1h;
        for (int idx = tid; idx < 4096; idx += 128) {
            int w = idx & 31, n = (idx >> 5) & 63, kz = idx >> 11;
            W1hw[kz * 2304 + n * 36 + w] = gw1h[idx];
        }
    }
    __syncthreads();

    const int geBase = blockIdx.x * 128;

    // ---- main loop: NO barriers inside ----------------------------------
    #pragma unroll 1
    for (int k = 0; k < 2; ++k) {
        const float* SB1k = SB1 + k * 64;
        const float* SB2k = SB2 + k * 32;
        const uint32_t w1hk = bW1h + k * 9216;
        const uint32_t w1lk = bW1l + k * 9216;
        const uint32_t w2hk = bW2h + k * 4608;
        const uint32_t w2lk = bW2l + k * 4608;

        // layer 1: H[32,64] = X @ W1^T  (Xh@Wh + Xh@Wl + Xl@Wh), acc init = bias
        float acc[2][8][4];
        #pragma unroll
        for (int nt = 0; nt < 8; ++nt) {
            float bb0 = SB1k[nt * 8 + 2 * cq];
            float bb1 = SB1k[nt * 8 + 2 * cq + 1];
            acc[0][nt][0] = bb0; acc[0][nt][1] = bb1;
            acc[0][nt][2] = bb0; acc[0][nt][3] = bb1;
            acc[1][nt][0] = bb0; acc[1][nt][1] = bb1;
            acc[1][nt][2] = bb0; acc[1][nt][3] = bb1;
        }

        #pragma unroll
        for (int kk = 0; kk < 4; ++kk) {
            uint32_t Al0[4], Al1[4];
            ldsm_x4(aXl + kk * 32, Al0);
            ldsm_x4(aXl + 2304 + kk * 32, Al1);
            #pragma unroll
            for (int nt = 0; nt < 8; ++nt) {
                uint32_t bh[2], bl[2];
                ldsm_x2(w1hk + nt * 1152 + kk * 32, bh);
                ldsm_x2(w1lk + nt * 1152 + kk * 32, bl);
                mma16816(acc[0][nt], Ah[0][kk], bh);
                mma16816(acc[1][nt], Ah[1][kk], bh);
                mma16816(acc[0][nt], Ah[0][kk], bl);
                mma16816(acc[1][nt], Ah[1][kk], bl);
                mma16816(acc[0][nt], Al0, bh);
                mma16816(acc[1][nt], Al1, bh);
            }
        }

        // epilogue 1: ELU, repack C fragments -> layer-2 A operands
        uint32_t A2h[2][4][4], A2l[2][4][4];
        #pragma unroll
        for (int mt = 0; mt < 2; ++mt) {
            #pragma unroll
            for (int kk = 0; kk < 4; ++kk) {
                float v00 = elu_f(acc[mt][2 * kk][0]);
                float v01 = elu_f(acc[mt][2 * kk][1]);
                float v10 = elu_f(acc[mt][2 * kk][2]);
                float v11 = elu_f(acc[mt][2 * kk][3]);
                float w00 = elu_f(acc[mt][2 * kk + 1][0]);
                float w01 = elu_f(acc[mt][2 * kk + 1][1]);
                float w10 = elu_f(acc[mt][2 * kk + 1][2]);
                float w11 = elu_f(acc[mt][2 * kk + 1][3]);
                split2(v00, v01, A2h[mt][kk][0], A2l[mt][kk][0]);
                split2(v10, v11, A2h[mt][kk][1], A2l[mt][kk][1]);
                split2(w00, w01, A2h[mt][kk][2], A2l[mt][kk][2]);
                split2(w10, w11, A2h[mt][kk][3], A2l[mt][kk][3]);
            }
        }

        // layer 2: O[32,32] = H @ W2^T  (Hh@Wh + Hh@Wl + Hl@Wh), acc init = bias
        float ac2[2][4][4];
        #pragma unroll
        for (int nt = 0; nt < 4; ++nt) {
            float bb0 = SB2k[nt * 8 + 2 * cq];
            float bb1 = SB2k[nt * 8 + 2 * cq + 1];
            ac2[0][nt][0] = bb0; ac2[0][nt][1] = bb1;
            ac2[0][nt][2] = bb0; ac2[0][nt][3] = bb1;
            ac2[1][nt][0] = bb0; ac2[1][nt][1] = bb1;
            ac2[1][nt][2] = bb0; ac2[1][nt][3] = bb1;
        }

        #pragma unroll
        for (int kk = 0; kk < 4; ++kk) {
            #pragma unroll
            for (int nt = 0; nt < 4; ++nt) {
                uint32_t bh[2], bl[2];
                ldsm_x2(w2hk + nt * 1152 + kk * 32, bh);
                ldsm_x2(w2lk + nt * 1152 + kk * 32, bl);
                mma16816(ac2[0][nt], A2h[0][kk], bh);
                mma16816(ac2[1][nt], A2h[1][kk], bh);
                mma16816(ac2[0][nt], A2h[0][kk], bl);
                mma16816(ac2[1][nt], A2h[1][kk], bl);
                mma16816(ac2[0][nt], A2l[0][kk], bh);
                mma16816(ac2[1][nt], A2l[1][kk], bh);
            }
        }

        // epilogue 2: ELU, channel-major store + register BN stats
        float sl[8], ql[8];
        #pragma unroll
        for (int j = 0; j < 8; ++j) { sl[j] = 0.f; ql[j] = 0.f; }
        #pragma unroll
        for (int mt = 0; mt < 2; ++mt) {
            const int r0 = geBase + R0 + mt * 16 + g;
            #pragma unroll
            for (int nt = 0; nt < 4; ++nt) {
                const int col = nt * 8 + 2 * cq;
                float v00 = elu_f(ac2[mt][nt][0]);
                float v01 = elu_f(ac2[mt][nt][1]);
                float v10 = elu_f(ac2[mt][nt][2]);
                float v11 = elu_f(ac2[mt][nt][3]);
                g_O[(size_t)(k * 32 + col) * BE_ + r0]         = v00;
                g_O[(size_t)(k * 32 + col + 1) * BE_ + r0]     = v01;
                g_O[(size_t)(k * 32 + col) * BE_ + r0 + 8]     = v10;
                g_O[(size_t)(k * 32 + col + 1) * BE_ + r0 + 8] = v11;
                sl[nt * 2]     += v00 + v10;
                ql[nt * 2]     += v00 * v00 + v10 * v10;
                sl[nt * 2 + 1] += v01 + v11;
                ql[nt * 2 + 1] += v01 * v01 + v11 * v11;
            }
        }
        #pragma unroll
        for (int j = 0; j < 8; ++j) {
            #pragma unroll
            for (int off = 4; off < 32; off <<= 1) {
                sl[j] += __shfl_xor_sync(0xffffffffu, sl[j], off);
                ql[j] += __shfl_xor_sync(0xffffffffu, ql[j], off);
            }
        }
        if (lid < 4) {
            #pragma unroll
            for (int nt = 0; nt < 4; ++nt) {
                atomicAdd(&SSUM[k * 32 + nt * 8 + 2 * lid],     sl[nt * 2]);
                atomicAdd(&SSQ [k * 32 + nt * 8 + 2 * lid],     ql[nt * 2]);
                atomicAdd(&SSUM[k * 32 + nt * 8 + 2 * lid + 1], sl[nt * 2 + 1]);
                atomicAdd(&SSQ [k * 32 + nt * 8 + 2 * lid + 1], ql[nt * 2 + 1]);
            }
        }
    }

    __syncthreads();
    if (tid < 64) { atomicAdd(&g_esum[tid], SSUM[tid]); atomicAdd(&g_esq[tid], SSQ[tid]); }
}

// ---------------------------------------------------------------------------
// D) fused post-pass: node_norm (blocks 0..1023) | edge_out (blocks 1024..3039)
//    Each block computes the tiny BN-affine locally from the global stats.
// ---------------------------------------------------------------------------
__global__ __launch_bounds__(256) void postpass(
    const float* __restrict__ et,
    const float* __restrict__ eg, const float* __restrict__ ebet,
    const float* __restrict__ vg, const float* __restrict__ vbet,
    float* __restrict__ dv, float* __restrict__ de)
{
    __shared__ float A[64], C[64];
    __shared__ float T[32 * 257];
    const int bx = blockIdx.x, tid = threadIdx.x;

    if (bx < 1024) {
        if (tid < 32) {
            const float inv_cnt = 1.f / 8192.f;
            float mu = g_nsum[tid] * inv_cnt;
            float var = g_nsq[tid] * inv_cnt - mu * mu;
            float a = vg[tid] * rsqrtf(var + 1e-5f);
            A[tid] = a; C[tid] = vbet[tid] - mu * a;
        }
        __syncthreads();
        int idx = bx * 256 + tid;
        int c = idx & 31;
        dv[idx] = g_ov[idx] * A[c] + C[c];
        return;
    }

    if (tid < 64) {
        const float inv_cnt = 1.f / (float)BE_;
        float mu = g_esum[tid] * inv_cnt;
        float var = g_esq[tid] * inv_cnt - mu * mu;
        float a = eg[tid] * rsqrtf(var + 1e-5f);
        A[tid] = a; C[tid] = ebet[tid] - mu * a;
    }
    __syncthreads();

    const int eb = bx - 1024;
    const int ge = eb * 256 + tid;
    float2 w = reinterpret_cast<const float2*>(et)[ge];
    #pragma unroll 8
    for (int oo = 0; oo < 32; ++oo) {
        float x0 = g_O[(size_t)oo * BE_ + ge];
        float x1 = g_O[(size_t)(32 + oo) * BE_ + ge];
        T[oo * 257 + tid] = (A[oo] * x0 + C[oo]) * w.x + (A[32 + oo] * x1 + C[32 + oo]) * w.y;
    }
    __syncthreads();
    float* outb = de + (size_t)eb * 8192;
    #pragma unroll 8
    for (int r = 0; r < 32; ++r) {
        int flat = r * 256 + tid;
        outb[flat] = T[(flat & 31) * 257 + (flat >> 5)];
    }
}

// ---------------------------------------------------------------------------
extern "C" void kernel_launch(void* const* d_in, const int* in_sizes, int n_in,
                              void* d_out, int out_size)
{
    const float* v0   = (const float*)d_in[0];
    const float* e0   = (const float*)d_in[1];
    const float* et   = (const float*)d_in[2];
    const float* vW1  = (const float*)d_in[3];
    const float* vb1  = (const float*)d_in[4];
    const float* vW2  = (const float*)d_in[5];
    const float* vb2  = (const float*)d_in[6];
    const float* vg   = (const float*)d_in[7];
    const float* vbet = (const float*)d_in[8];
    const float* eW1  = (const float*)d_in[9];
    const float* eb1  = (const float*)d_in[10];
    const float* eW2  = (const float*)d_in[11];
    const float* eb2  = (const float*)d_in[12];
    const float* eg   = (const float*)d_in[13];
    const float* ebet = (const float*)d_in[14];
    float* out = (float*)d_out;

    cudaFuncSetAttribute(edge_hmma, cudaFuncAttributeMaxDynamicSharedMemorySize, EH_SMEM);
    cudaFuncSetAttribute(edge_hmma, cudaFuncAttributePreferredSharedMemoryCarveout, 100);

    prepass<<<5088, 256>>>(e0, eW1, eW2, out + ZERO_OFF);
    node_mlp1<<<128, 64>>>(vW1, vb1, vW2, vb2);
    edge_hmma<<<4032, 128, EH_SMEM>>>(v0, eb1, eb2);
    postpass<<<3040, 256>>>(et, eg, ebet, vg, vbet, out, out + DE_OFF);

    (void)in_sizes; (void)n_in; (void)out_size;
}